// round 2
// baseline (speedup 1.0000x reference)
#include <cuda_runtime.h>
#include <cstdint>

// Problem constants (fixed shapes per reference setup_inputs)
#define B_SZ 64
#define T_SZ 1024
#define H_SZ 1024
#define K_TAGS 16
#define START_TAG 14
#define STOP_TAG 15

// Scratch (no cudaMalloc allowed): logits [B,T,16] + per-sequence partials
__device__ float g_logits[B_SZ * T_SZ * K_TAGS];
__device__ float g_part[B_SZ];

// ---------------- f32x2 packed helpers (Blackwell) ----------------
__device__ __forceinline__ unsigned long long pack2(float a, float b) {
    unsigned long long r;
    asm("mov.b64 %0, {%1, %2};" : "=l"(r) : "f"(a), "f"(b));
    return r;
}
__device__ __forceinline__ void unpack2(unsigned long long v, float& a, float& b) {
    asm("mov.b64 {%0, %1}, %2;" : "=f"(a), "=f"(b) : "l"(v));
}
__device__ __forceinline__ void fma2(unsigned long long& acc, unsigned long long a,
                                     unsigned long long b) {
    asm("fma.rn.f32x2 %0, %1, %2, %0;" : "+l"(acc) : "l"(a), "l"(b));
}
__device__ __forceinline__ unsigned long long add2(unsigned long long a, unsigned long long b) {
    unsigned long long r;
    asm("add.rn.f32x2 %0, %1, %2;" : "=l"(r) : "l"(a), "l"(b));
    return r;
}

// ---------------------------------------------------------------------------
// Kernel 1: logits[b,t,:] = lstm_out[b,t,:] @ W + bias     (65536 x 1024 x 16)
//
// Block = 256 threads (8 warps), each warp owns 4 rows -> 32 rows/block.
// Lane = (r, g): r = lane>>3 picks the row, g = lane&7 picks the h-residue;
// each lane iterates h = 8*i + g. W is staged through a STATIC 40 KB SMEM
// tile in 2 phases of 512 h-rows, row stride 20 floats (80 B): bank base =
// 20*g mod 32 -> 8 disjoint 16B lines per LDS.128 warp instruction with
// 4-way broadcast across the r-duplicates (conflict-free, 1 crossbar phase).
// Accumulators are j-pairs held in packed f32x2.
// ---------------------------------------------------------------------------
__global__ void __launch_bounds__(256) gemm_kernel(const float* __restrict__ X,
                                                   const float* __restrict__ W,
                                                   const float* __restrict__ bias) {
    __shared__ float Wsm[512 * 20];  // 40960 B, static (no attribute opt-in needed)

    const int lane = threadIdx.x & 31;
    const int warp = threadIdx.x >> 5;
    const int r = lane >> 3;
    const int g = lane & 7;
    const int row = blockIdx.x * 32 + warp * 4 + r;
    const float* xrow = X + (size_t)row * H_SZ;

    unsigned long long acc[8];
#pragma unroll
    for (int jp = 0; jp < 8; jp++) acc[jp] = 0ULL;

#pragma unroll 1
    for (int ph = 0; ph < 2; ph++) {
        __syncthreads();  // WAR: previous phase's readers done before overwrite
        for (int idx = threadIdx.x; idx < 512 * K_TAGS; idx += blockDim.x)
            Wsm[(idx >> 4) * 20 + (idx & 15)] = W[ph * 512 * K_TAGS + idx];
        __syncthreads();

        const float* xph = xrow + ph * 512;
#pragma unroll 1
        for (int i2 = 0; i2 < 64; i2 += 8) {
            float xv[8];
#pragma unroll
            for (int u = 0; u < 8; u++) xv[u] = xph[(i2 + u) * 8 + g];  // batched LDG (MLP=8)
#pragma unroll
            for (int u = 0; u < 8; u++) {
                const int hl = (i2 + u) * 8 + g;  // local h within phase
                const ulonglong2* wp = reinterpret_cast<const ulonglong2*>(Wsm + hl * 20);
                ulonglong2 w0 = wp[0];
                ulonglong2 w1 = wp[1];
                ulonglong2 w2 = wp[2];
                ulonglong2 w3 = wp[3];
                unsigned long long xx = pack2(xv[u], xv[u]);
                fma2(acc[0], xx, w0.x);
                fma2(acc[1], xx, w0.y);
                fma2(acc[2], xx, w1.x);
                fma2(acc[3], xx, w1.y);
                fma2(acc[4], xx, w2.x);
                fma2(acc[5], xx, w2.y);
                fma2(acc[6], xx, w3.x);
                fma2(acc[7], xx, w3.y);
            }
        }
    }

    // Reduce over the 8 g-lanes that share a row (lanes r*8 .. r*8+7)
#pragma unroll
    for (int m = 1; m <= 4; m <<= 1) {
#pragma unroll
        for (int jp = 0; jp < 8; jp++)
            acc[jp] = add2(acc[jp], __shfl_xor_sync(0xffffffffu, acc[jp], m));
    }

    if (g == 0) {
        float* op = g_logits + (size_t)row * K_TAGS;
#pragma unroll
        for (int jp = 0; jp < 8; jp++) {
            float lo, hi;
            unpack2(acc[jp], lo, hi);
            float2 v = make_float2(lo + __ldg(&bias[2 * jp]), hi + __ldg(&bias[2 * jp + 1]));
            reinterpret_cast<float2*>(op)[jp] = v;
        }
    }
}

// ---------------------------------------------------------------------------
// Kernel 2: per-sequence CRF forward scan (linear domain) + gold path score.
// One warp per sequence. lane = (j, h): j = lane&15 output tag, h = lane>>4
// half of the i-reduction. ET[i][j] = exp(trans[i][j]) cached in registers
// (8 per lane). alpha double-buffered in SMEM; rescale-by-max every 8 steps
// with logZ accumulation (worst-case growth < e^62 per window: safe in fp32).
// Masked transitions (-1000) become exp() == 0 exactly -> correct.
// ---------------------------------------------------------------------------
__global__ void crf_kernel(const float* __restrict__ trans, const int* __restrict__ tags) {
    __shared__ float trans_sm[K_TAGS * K_TAGS];
    __shared__ __align__(16) float alpha_sm[2][K_TAGS];

    const int lane = threadIdx.x;
    const int b = blockIdx.x;
    const int j = lane & 15;
    const int h = lane >> 4;

    for (int k = lane; k < 256; k += 32) trans_sm[k] = trans[k];
    __syncwarp();

    // ---- gold path score ----
    const int* tgs = tags + b * T_SZ;
    const float* lg = g_logits + (size_t)b * T_SZ * K_TAGS;
    float real = 0.f;
#pragma unroll 4
    for (int it = 0; it < 32; it++) {
        int t = it * 32 + lane;
        int tg = tgs[t];
        int pt = (t == 0) ? START_TAG : tgs[t - 1];
        real += lg[t * K_TAGS + tg] + trans_sm[pt * K_TAGS + tg];
    }
#pragma unroll
    for (int m = 16; m; m >>= 1) real += __shfl_xor_sync(0xffffffffu, real, m);
    real += trans_sm[tgs[T_SZ - 1] * K_TAGS + STOP_TAG];  // same in all lanes

    // ---- ET registers: exp(trans[i][j]) for i in [8h, 8h+8) ----
    float et[8];
#pragma unroll
    for (int k = 0; k < 8; k++) et[k] = __expf(trans_sm[(8 * h + k) * K_TAGS + j]);

    if (h == 0) alpha_sm[0][j] = 1.0f;  // log-domain prev = 0
    __syncwarp();

    // prefetch first 4 observations
    float ob[4];
#pragma unroll
    for (int u = 0; u < 4; u++) ob[u] = lg[u * K_TAGS + j];

    float logZ = 0.f;
#pragma unroll 1
    for (int t0 = 0; t0 < T_SZ; t0 += 4) {
        float nxt[4];
#pragma unroll
        for (int u = 0; u < 4; u++) {
            int tn = t0 + 4 + u;
            nxt[u] = (tn < T_SZ) ? lg[tn * K_TAGS + j] : 0.f;
        }
#pragma unroll
        for (int u = 0; u < 4; u++) {
            const int t = t0 + u;
            const int p = t & 1;
            float eo = __expf(ob[u]);
            const float4* ap = reinterpret_cast<const float4*>(&alpha_sm[p][h * 8]);
            float4 a0 = ap[0];
            float4 a1 = ap[1];
            float dot = ((a0.x * et[0] + a0.y * et[1]) + (a0.z * et[2] + a0.w * et[3])) +
                        ((a1.x * et[4] + a1.y * et[5]) + (a1.z * et[6] + a1.w * et[7]));
            dot += __shfl_xor_sync(0xffffffffu, dot, 16);  // combine the two i-halves
            float na = dot * eo;
            if ((t & 7) == 7) {  // periodic rescale
                float mx = na;
#pragma unroll
                for (int m = 1; m <= 8; m <<= 1)
                    mx = fmaxf(mx, __shfl_xor_sync(0xffffffffu, mx, m));
                na = na / mx;
                logZ += __logf(mx);
            }
            if (h == 0) alpha_sm[p ^ 1][j] = na;
            __syncwarp();
        }
#pragma unroll
        for (int u = 0; u < 4; u++) ob[u] = nxt[u];
    }

    // ---- finalize: total = logZ + c + log(sum_j alpha_j * exp(trans[j,STOP]-c)) ----
    float av = alpha_sm[0][j];  // last write (t=1023, p=1) landed in slot 0
    float ts = trans_sm[j * K_TAGS + STOP_TAG];
    float c = ts;
#pragma unroll
    for (int m = 1; m <= 8; m <<= 1) c = fmaxf(c, __shfl_xor_sync(0xffffffffu, c, m));
    float s = av * __expf(ts - c);
#pragma unroll
    for (int m = 1; m <= 8; m <<= 1) s += __shfl_xor_sync(0xffffffffu, s, m);
    float total = logZ + c + __logf(s);

    if (lane == 0) g_part[b] = total - real;
}

// ---------------------------------------------------------------------------
// Kernel 3: deterministic reduction of 64 per-sequence partials -> scalar.
// ---------------------------------------------------------------------------
__global__ void reduce_kernel(float* __restrict__ out) {
    const int lane = threadIdx.x;  // 32 threads
    float v = g_part[lane] + g_part[lane + 32];
#pragma unroll
    for (int m = 16; m; m >>= 1) v += __shfl_xor_sync(0xffffffffu, v, m);
    if (lane == 0) out[0] = v;
}

// ---------------------------------------------------------------------------
extern "C" void kernel_launch(void* const* d_in, const int* in_sizes, int n_in,
                              void* d_out, int out_size) {
    const float* X = (const float*)d_in[0];      // lstm_out [64,1024,1024]
    const float* W = (const float*)d_in[1];      // [1024,16]
    const float* bias = (const float*)d_in[2];   // [16]
    const float* trans = (const float*)d_in[3];  // [16,16]
    const int* tags = (const int*)d_in[4];       // [64,1024]

    gemm_kernel<<<(B_SZ * T_SZ) / 32, 256>>>(X, W, bias);
    crf_kernel<<<B_SZ, 32>>>(trans, tags);
    reduce_kernel<<<1, 32>>>((float*)d_out);
}

// round 4
// speedup vs baseline: 1.0310x; 1.0310x over previous
#include <cuda_runtime.h>
#include <cstdint>

#define B_SZ 64
#define T_SZ 1024
#define H_SZ 1024
#define K_TAGS 16
#define START_TAG 14
#define STOP_TAG 15

__device__ float g_logits[B_SZ * T_SZ * K_TAGS];
__device__ float g_part[B_SZ];

// ---------------- f32x2 packed helpers (Blackwell) ----------------
__device__ __forceinline__ unsigned long long pack2(float a, float b) {
    unsigned long long r;
    asm("mov.b64 %0, {%1, %2};" : "=l"(r) : "f"(a), "f"(b));
    return r;
}
__device__ __forceinline__ void unpack2(unsigned long long v, float& a, float& b) {
    asm("mov.b64 {%0, %1}, %2;" : "=f"(a), "=f"(b) : "l"(v));
}
__device__ __forceinline__ void fma2(unsigned long long& acc, unsigned long long a,
                                     unsigned long long b) {
    asm("fma.rn.f32x2 %0, %1, %2, %0;" : "+l"(acc) : "l"(a), "l"(b));
}
__device__ __forceinline__ unsigned long long add2(unsigned long long a, unsigned long long b) {
    unsigned long long r;
    asm("add.rn.f32x2 %0, %1, %2;" : "=l"(r) : "l"(a), "l"(b));
    return r;
}

// ---------------------------------------------------------------------------
// Kernel 1: logits = X @ W + bias  (65536 x 1024 x 16)
// Warp = 32 distinct h-lanes; each lane accumulates 4 rows x 16 outputs in
// 32 f32x2 regs -> each 64B W smem read feeds 64 MACs (1.25 B/MAC).
// W staged in 2 phases of 512 h-rows, stride 20 floats (conflict-free
// LDS.128). Epilogue: 5-level halving shfl tree; lane (r=lane>>3, jp=lane&7)
// ends owning its own f32x2 -> 256B coalesced STG per warp.
// ---------------------------------------------------------------------------
__global__ void __launch_bounds__(256) gemm_kernel(const float* __restrict__ X,
                                                   const float* __restrict__ W,
                                                   const float* __restrict__ bias) {
    __shared__ float Wsm[512 * 20];  // 40 KB static

    const int lane = threadIdx.x & 31;
    const int warp = threadIdx.x >> 5;
    const int row0 = blockIdx.x * 32 + warp * 4;
    const float* xr = X + (size_t)row0 * H_SZ;

    unsigned long long acc[4][8];
#pragma unroll
    for (int r = 0; r < 4; r++)
#pragma unroll
        for (int jp = 0; jp < 8; jp++) acc[r][jp] = 0ULL;

#pragma unroll 1
    for (int ph = 0; ph < 2; ph++) {
        __syncthreads();  // WAR vs previous phase readers
        for (int idx = threadIdx.x; idx < 512 * K_TAGS; idx += blockDim.x)
            Wsm[(idx >> 4) * 20 + (idx & 15)] = W[ph * 512 * K_TAGS + idx];
        __syncthreads();

        const float* xp = xr + ph * 512;
#pragma unroll 2
        for (int i = 0; i < 16; i++) {
            const int hl = i * 32 + lane;
            float xv[4];
#pragma unroll
            for (int r = 0; r < 4; r++) xv[r] = xp[r * H_SZ + hl];  // coalesced, MLP=4

            const ulonglong2* wp = reinterpret_cast<const ulonglong2*>(Wsm + hl * 20);
            ulonglong2 w0 = wp[0];
            ulonglong2 w1 = wp[1];
            ulonglong2 w2 = wp[2];
            ulonglong2 w3 = wp[3];
            unsigned long long ws[8] = {w0.x, w0.y, w1.x, w1.y, w2.x, w2.y, w3.x, w3.y};

#pragma unroll
            for (int r = 0; r < 4; r++) {
                unsigned long long xx = pack2(xv[r], xv[r]);
#pragma unroll
                for (int jp = 0; jp < 8; jp++) fma2(acc[r][jp], xx, ws[jp]);
            }
        }
    }

    // ---- halving butterfly reduction over 32 lanes ----
    const int b4 = (lane >> 4) & 1;
    const int b3 = (lane >> 3) & 1;
    const int b2 = (lane >> 2) & 1;
    const int b1 = (lane >> 1) & 1;
    const int b0 = lane & 1;

    unsigned long long k2[2][8];
#pragma unroll
    for (int k = 0; k < 2; k++)
#pragma unroll
        for (int jp = 0; jp < 8; jp++) {
            unsigned long long snd = acc[2 * (1 - b4) + k][jp];
            k2[k][jp] = add2(acc[2 * b4 + k][jp], __shfl_xor_sync(0xffffffffu, snd, 16));
        }
    unsigned long long k3[8];
#pragma unroll
    for (int jp = 0; jp < 8; jp++) {
        unsigned long long snd = k2[1 - b3][jp];
        k3[jp] = add2(k2[b3][jp], __shfl_xor_sync(0xffffffffu, snd, 8));
    }
    unsigned long long k4[4];
#pragma unroll
    for (int m = 0; m < 4; m++) {
        unsigned long long snd = k3[4 * (1 - b2) + m];
        k4[m] = add2(k3[4 * b2 + m], __shfl_xor_sync(0xffffffffu, snd, 4));
    }
    unsigned long long k5[2];
#pragma unroll
    for (int m = 0; m < 2; m++) {
        unsigned long long snd = k4[2 * (1 - b1) + m];
        k5[m] = add2(k4[2 * b1 + m], __shfl_xor_sync(0xffffffffu, snd, 2));
    }
    unsigned long long snd = k5[1 - b0];
    unsigned long long res = add2(k5[b0], __shfl_xor_sync(0xffffffffu, snd, 1));

    float lo, hi;
    unpack2(res, lo, hi);
    float2 bz = reinterpret_cast<const float2*>(bias)[lane & 7];
    float2 out = make_float2(lo + bz.x, hi + bz.y);
    reinterpret_cast<float2*>(g_logits + (size_t)(row0 + (lane >> 3)) * K_TAGS)[lane & 7] = out;
}

// ---------------------------------------------------------------------------
// Kernel 2: CRF loss, forward/backward split. Block = 1 sequence, 2 warps.
// warp 0: a_512 forward over t=0..511; warp 1: w_512 backward over
// t=1023..512, seeded IN LOG-SHIFTED FORM: w_1024[i] = exp(trans[i,STOP]-c0),
// logZ_b = c0 (R3 bugfix: trans[:,STOP] == -1000 for all i, so the unshifted
// seed exp(-1000) was identically 0 -> 0/0 NaN at the first rescale).
// Z = logZ_f + logZ_b + log(a_512 . w_512). Per-step exchange is pure shfl.
// ---------------------------------------------------------------------------
__global__ void crf_kernel(const float* __restrict__ trans, const int* __restrict__ tags) {
    __shared__ float trans_sm[K_TAGS * K_TAGS];
    __shared__ float vec_sm[2][K_TAGS];
    __shared__ float sc_sm[2];
    __shared__ float real_sm[2];

    const int tid = threadIdx.x;
    const int wid = tid >> 5;
    const int lane = tid & 31;
    const int b = blockIdx.x;
    const int j = lane & 15;  // tag index (fwd: dest tag; bwd: source tag)
    const int h = lane >> 4;  // which 8-wide half of the 16-sum this lane does

    for (int k = tid; k < 256; k += 64) trans_sm[k] = trans[k];
    __syncthreads();

    const int* tgs = tags + b * T_SZ;
    const float* lg = g_logits + (size_t)b * T_SZ * K_TAGS;

    if (wid == 0) {
        // ---- gold-path partial over t in [0, 512) ----
        float real = 0.f;
#pragma unroll 4
        for (int it = 0; it < 16; it++) {
            int t = it * 32 + lane;
            int tg = tgs[t];
            int pt = (t == 0) ? START_TAG : tgs[t - 1];
            real += lg[t * K_TAGS + tg] + trans_sm[pt * K_TAGS + tg];
        }
#pragma unroll
        for (int m = 16; m; m >>= 1) real += __shfl_xor_sync(0xffffffffu, real, m);
        if (lane == 0) real_sm[0] = real;

        // ---- forward scan ----
        float et[8];
#pragma unroll
        for (int k = 0; k < 8; k++) et[k] = __expf(trans_sm[(8 * h + k) * K_TAGS + j]);

        float aj = 1.0f;  // exp(0) init
        float logZ = 0.f;
        float ob[4];
#pragma unroll
        for (int u = 0; u < 4; u++) ob[u] = lg[u * K_TAGS + j];

#pragma unroll 1
        for (int t0 = 0; t0 < 512; t0 += 4) {
            float nxt[4];
#pragma unroll
            for (int u = 0; u < 4; u++) {
                int tn = t0 + 4 + u;
                nxt[u] = (tn < 512) ? lg[tn * K_TAGS + j] : 0.f;
            }
#pragma unroll
            for (int u = 0; u < 4; u++) {
                const int t = t0 + u;
                float eo = __expf(ob[u]);
                float av[8];
#pragma unroll
                for (int k = 0; k < 8; k++)
                    av[k] = __shfl_sync(0xffffffffu, aj, 8 * h + k);
                float dot = ((av[0] * et[0] + av[1] * et[1]) + (av[2] * et[2] + av[3] * et[3])) +
                            ((av[4] * et[4] + av[5] * et[5]) + (av[6] * et[6] + av[7] * et[7]));
                dot += __shfl_xor_sync(0xffffffffu, dot, 16);
                aj = dot * eo;
                if ((t & 7) == 7) {
                    float mx = aj;
#pragma unroll
                    for (int m = 1; m <= 8; m <<= 1)
                        mx = fmaxf(mx, __shfl_xor_sync(0xffffffffu, mx, m));
                    mx = fmaxf(mx, 1e-30f);
                    aj /= mx;
                    logZ += __logf(mx);
                }
            }
#pragma unroll
            for (int u = 0; u < 4; u++) ob[u] = nxt[u];
        }
        float mx = aj;
#pragma unroll
        for (int m = 1; m <= 8; m <<= 1) mx = fmaxf(mx, __shfl_xor_sync(0xffffffffu, mx, m));
        mx = fmaxf(mx, 1e-30f);
        aj /= mx;
        logZ += __logf(mx);
        if (h == 0) vec_sm[0][j] = aj;
        if (lane == 0) sc_sm[0] = logZ;
    } else {
        // ---- gold-path partial over t in [512, 1024) + STOP term ----
        float real = 0.f;
#pragma unroll 4
        for (int it = 0; it < 16; it++) {
            int t = 512 + it * 32 + lane;
            int tg = tgs[t];
            int pt = tgs[t - 1];
            real += lg[t * K_TAGS + tg] + trans_sm[pt * K_TAGS + tg];
        }
#pragma unroll
        for (int m = 16; m; m >>= 1) real += __shfl_xor_sync(0xffffffffu, real, m);
        if (lane == 0) real_sm[1] = real + trans_sm[tgs[T_SZ - 1] * K_TAGS + STOP_TAG];

        // ---- backward scan (lane j = source tag i) ----
        float etb[8];
#pragma unroll
        for (int k = 0; k < 8; k++) etb[k] = __expf(trans_sm[j * K_TAGS + 8 * h + k]);

        // R3 FIX: max-shifted seed. ts == -1000 for all i here, so c0 = -1000,
        // wi = 1 for all lanes, logZ starts at -1000 (cancels exactly in Z).
        float ts = trans_sm[j * K_TAGS + STOP_TAG];
        float c0 = ts;
#pragma unroll
        for (int m = 1; m <= 8; m <<= 1) c0 = fmaxf(c0, __shfl_xor_sync(0xffffffffu, c0, m));
        float wi = __expf(ts - c0);
        float logZ = c0;

        float ob[4];
#pragma unroll
        for (int u = 0; u < 4; u++) ob[u] = lg[(1023 - u) * K_TAGS + j];

#pragma unroll 1
        for (int s0 = 0; s0 < 512; s0 += 4) {
            float nxt[4];
#pragma unroll
            for (int u = 0; u < 4; u++) {
                int sn = s0 + 4 + u;  // steps from the end
                nxt[u] = (sn < 512) ? lg[(1023 - sn) * K_TAGS + j] : 0.f;
            }
#pragma unroll
            for (int u = 0; u < 4; u++) {
                const int s = s0 + u;
                float ui = wi * __expf(ob[u]);  // (eo_t o w_{t+1})[i]
                float uv[8];
#pragma unroll
                for (int k = 0; k < 8; k++)
                    uv[k] = __shfl_sync(0xffffffffu, ui, 8 * h + k);
                float dot = ((uv[0] * etb[0] + uv[1] * etb[1]) + (uv[2] * etb[2] + uv[3] * etb[3])) +
                            ((uv[4] * etb[4] + uv[5] * etb[5]) + (uv[6] * etb[6] + uv[7] * etb[7]));
                dot += __shfl_xor_sync(0xffffffffu, dot, 16);
                wi = dot;
                if ((s & 7) == 7) {
                    float mx = wi;
#pragma unroll
                    for (int m = 1; m <= 8; m <<= 1)
                        mx = fmaxf(mx, __shfl_xor_sync(0xffffffffu, mx, m));
                    mx = fmaxf(mx, 1e-30f);
                    wi /= mx;
                    logZ += __logf(mx);
                }
            }
#pragma unroll
            for (int u = 0; u < 4; u++) ob[u] = nxt[u];
        }
        float mx = wi;
#pragma unroll
        for (int m = 1; m <= 8; m <<= 1) mx = fmaxf(mx, __shfl_xor_sync(0xffffffffu, mx, m));
        mx = fmaxf(mx, 1e-30f);
        wi /= mx;
        logZ += __logf(mx);
        if (h == 0) vec_sm[1][j] = wi;
        if (lane == 0) sc_sm[1] = logZ;
    }

    __syncthreads();

    if (wid == 0) {
        float p = vec_sm[0][j] * vec_sm[1][j];
#pragma unroll
        for (int m = 1; m <= 8; m <<= 1) p += __shfl_xor_sync(0xffffffffu, p, m);
        if (lane == 0) {
            float total = sc_sm[0] + sc_sm[1] + __logf(p);
            g_part[b] = total - (real_sm[0] + real_sm[1]);
        }
    }
}

// ---------------------------------------------------------------------------
// Kernel 3: deterministic reduction of 64 partials -> scalar.
// ---------------------------------------------------------------------------
__global__ void reduce_kernel(float* __restrict__ out) {
    const int lane = threadIdx.x;
    float v = g_part[lane] + g_part[lane + 32];
#pragma unroll
    for (int m = 16; m; m >>= 1) v += __shfl_xor_sync(0xffffffffu, v, m);
    if (lane == 0) out[0] = v;
}

// ---------------------------------------------------------------------------
extern "C" void kernel_launch(void* const* d_in, const int* in_sizes, int n_in,
                              void* d_out, int out_size) {
    const float* X = (const float*)d_in[0];
    const float* W = (const float*)d_in[1];
    const float* bias = (const float*)d_in[2];
    const float* trans = (const float*)d_in[3];
    const int* tags = (const int*)d_in[4];

    gemm_kernel<<<(B_SZ * T_SZ) / 32, 256>>>(X, W, bias);
    crf_kernel<<<B_SZ, 64>>>(trans, tags);
    reduce_kernel<<<1, 32>>>((float*)d_out);
}